// round 7
// baseline (speedup 1.0000x reference)
#include <cuda_runtime.h>
#include <cuda_bf16.h>
#include <math.h>
#include <stdint.h>

#define NN 4096
#define DD 256
#define KK 8
#define NTILE 32              // 4096/128
#define NCTAS (NTILE * (NTILE + 1) / 2)   // 528 upper-triangle tiles

// ---------------------------------------------------------------------------
// Scratch (static __device__, no allocs)
// ---------------------------------------------------------------------------
__device__ float g_sim[(size_t)NN * NN];                  // 64 MB
__device__ __nv_bfloat16 g_hi[(size_t)NN * DD];           // 2 MB
__device__ __nv_bfloat16 g_lo[(size_t)NN * DD];           // 2 MB
__device__ float4 g_row[NN];                              // per-row results
__device__ unsigned int g_cnt;                            // completion counter

// ---------------------------------------------------------------------------
// helpers
// ---------------------------------------------------------------------------
__device__ __forceinline__ uint32_t smem_u32(const void* p) {
    uint32_t a;
    asm("{ .reg .u64 t; cvta.to.shared.u64 t, %1; cvt.u32.u64 %0, t; }"
        : "=r"(a) : "l"(p));
    return a;
}
#define SWZ128(x) ((x) ^ (((x) >> 3) & 0x70))

__device__ __forceinline__ void cp_async16(uint32_t saddr, const void* gaddr) {
    asm volatile("cp.async.cg.shared.global [%0], [%1], 16;"
                 :: "r"(saddr), "l"(gaddr) : "memory");
}
#define CP_COMMIT() asm volatile("cp.async.commit_group;" ::: "memory")
#define CP_WAIT(n)  asm volatile("cp.async.wait_group %0;" :: "n"(n) : "memory")

__device__ __forceinline__ void ldmat_x4(uint32_t& r0, uint32_t& r1,
                                         uint32_t& r2, uint32_t& r3, uint32_t a) {
    asm volatile("ldmatrix.sync.aligned.m8n8.x4.shared.b16 {%0,%1,%2,%3}, [%4];"
                 : "=r"(r0), "=r"(r1), "=r"(r2), "=r"(r3) : "r"(a));
}

__device__ __forceinline__ void mma_bf16(float* c, const uint32_t* a, const uint32_t* b) {
    asm volatile("mma.sync.aligned.m16n8k16.row.col.f32.bf16.bf16.f32 "
                 "{%0,%1,%2,%3}, {%4,%5,%6,%7}, {%8,%9}, {%0,%1,%2,%3};"
                 : "+f"(c[0]), "+f"(c[1]), "+f"(c[2]), "+f"(c[3])
                 : "r"(a[0]), "r"(a[1]), "r"(a[2]), "r"(a[3]),
                   "r"(b[0]), "r"(b[1]));
}

// ---------------------------------------------------------------------------
// Kernel 0: bf16 hi/lo split; 1 float4 / thread for max TLP.
// ---------------------------------------------------------------------------
__global__ void __launch_bounds__(256) split_bf16(const float* __restrict__ X) {
    const int gid = blockIdx.x * 256 + threadIdx.x;       // one float4 (4 elems)
    float4 a = ((const float4*)X)[gid];

    __nv_bfloat162 h01 = __float22bfloat162_rn(make_float2(a.x, a.y));
    __nv_bfloat162 h23 = __float22bfloat162_rn(make_float2(a.z, a.w));
    float2 f01 = __bfloat1622float2(h01), f23 = __bfloat1622float2(h23);
    __nv_bfloat162 l01 = __float22bfloat162_rn(make_float2(a.x - f01.x, a.y - f01.y));
    __nv_bfloat162 l23 = __float22bfloat162_rn(make_float2(a.z - f23.x, a.w - f23.y));

    uint2 hv, lv;
    hv.x = *(uint32_t*)&h01; hv.y = *(uint32_t*)&h23;
    lv.x = *(uint32_t*)&l01; lv.y = *(uint32_t*)&l23;
    ((uint2*)g_hi)[gid] = hv;
    ((uint2*)g_lo)[gid] = lv;
}

// ---------------------------------------------------------------------------
// Kernel 1: symmetric bf16x3 GEMM, 4 warps, warp tile 64x64, 3-stage cp.async.
// 1D grid of exactly 528 live CTAs; triangular decode to (br, bc).
// ---------------------------------------------------------------------------
extern __shared__ unsigned char dynsmem[];   // 96 KB: 3 x (16K A + 16K B)

__global__ void __launch_bounds__(128, 2) gemm_mma() {
    // decode linear tile id -> (br, bc) with bc >= br
    int t = blockIdx.x;
    int br = 0;
    {
        int rem = t;
        #pragma unroll 1
        while (rem >= NTILE - br) { rem -= NTILE - br; br++; }
        t = rem;
    }
    const int bc = br + t;

    const int tid = threadIdx.x;
    const int wid = tid >> 5, lid = tid & 31;
    const int wr = wid >> 1, wc = wid & 1;      // 2 x 2 warp grid

    const uint32_t sbase = smem_u32(dynsmem);

    float acc[4][8][4];
    #pragma unroll
    for (int mi = 0; mi < 4; mi++)
        #pragma unroll
        for (int ni = 0; ni < 8; ni++)
            #pragma unroll
            for (int q = 0; q < 4; q++) acc[mi][ni][q] = 0.f;

    int lrow[8], lsg[8];
    uint32_t soff[8];
    #pragma unroll
    for (int it = 0; it < 8; it++) {
        int idx = tid + it * 128;
        lrow[it] = idx >> 3;
        lsg[it]  = idx & 7;
        soff[it] = SWZ128((uint32_t)(lrow[it] * 128 + lsg[it] * 16));
    }

    const __nv_bfloat16* Asrc[3] = { g_hi, g_hi, g_lo };
    const __nv_bfloat16* Bsrc[3] = { g_hi, g_lo, g_hi };

    auto issue = [&](int c) {
        const int seg = c >> 2, colb = (c & 3) * 64;
        const char* pa = (const char*)Asrc[seg];
        const char* pb = (const char*)Bsrc[seg];
        const uint32_t sb = sbase + (uint32_t)(c % 3) * 32768u;
        #pragma unroll
        for (int it = 0; it < 8; it++) {
            size_t ao = ((size_t)(br * 128 + lrow[it]) * DD + colb) * 2 + lsg[it] * 16;
            size_t bo = ((size_t)(bc * 128 + lrow[it]) * DD + colb) * 2 + lsg[it] * 16;
            cp_async16(sb + soff[it], pa + ao);
            cp_async16(sb + 16384u + soff[it], pb + bo);
        }
        CP_COMMIT();
    };

    issue(0);
    issue(1);

    for (int c = 0; c < 12; c++) {
        if (c + 2 < 12) { CP_WAIT(1); }
        else if (c == 10) { CP_WAIT(1); }
        else { CP_WAIT(0); }
        __syncthreads();
        if (c + 2 < 12) issue(c + 2);

        const uint32_t sA = sbase + (uint32_t)(c % 3) * 32768u;
        const uint32_t sB = sA + 16384u;
        const int sub = lid >> 3;
        const int l8  = lid & 7;

        #pragma unroll
        for (int kk = 0; kk < 4; kk++) {
            const int kbase = kk * 16;
            uint32_t bfr[8][2];
            #pragma unroll
            for (int nj = 0; nj < 4; nj++) {
                int n  = wc * 64 + nj * 16 + l8 + (sub >> 1) * 8;
                int kh = kbase + (sub & 1) * 8;
                uint32_t addr = sB + SWZ128((uint32_t)(n * 128 + kh * 2));
                uint32_t r0, r1, r2, r3;
                ldmat_x4(r0, r1, r2, r3, addr);
                bfr[nj * 2 + 0][0] = r0; bfr[nj * 2 + 0][1] = r1;
                bfr[nj * 2 + 1][0] = r2; bfr[nj * 2 + 1][1] = r3;
            }
            uint32_t afr[4][4];
            #pragma unroll
            for (int mi = 0; mi < 4; mi++) {
                int r  = wr * 64 + mi * 16 + l8 + (sub & 1) * 8;
                int kh = kbase + (sub >> 1) * 8;
                uint32_t addr = sA + SWZ128((uint32_t)(r * 128 + kh * 2));
                ldmat_x4(afr[mi][0], afr[mi][1], afr[mi][2], afr[mi][3], addr);
            }
            #pragma unroll
            for (int mi = 0; mi < 4; mi++)
                #pragma unroll
                for (int ni = 0; ni < 8; ni++)
                    mma_bf16(acc[mi][ni], afr[mi], bfr[ni]);
        }
    }
    __syncthreads();

    // ----- direct stores (upper-triangle tile, row-major) -----
    const int qr = lid >> 2, qc = lid & 3;
    #pragma unroll
    for (int mi = 0; mi < 4; mi++) {
        int row = br * 128 + wr * 64 + mi * 16 + qr;
        #pragma unroll
        for (int ni = 0; ni < 8; ni++) {
            int col = bc * 128 + wc * 64 + ni * 8 + 2 * qc;
            *(float2*)&g_sim[(size_t)row * NN + col] =
                make_float2(acc[mi][ni][0], acc[mi][ni][1]);
            *(float2*)&g_sim[(size_t)(row + 8) * NN + col] =
                make_float2(acc[mi][ni][2], acc[mi][ni][3]);
        }
    }

    // ----- mirror stores: two 64-col halves via 64x132 smem transpose -----
    if (bc > br) {
        float* tr = (float*)dynsmem;
        #pragma unroll
        for (int h = 0; h < 2; h++) {
            __syncthreads();
            if (wc == h) {
                #pragma unroll
                for (int mi = 0; mi < 4; mi++) {
                    int r = wr * 64 + mi * 16 + qr;
                    #pragma unroll
                    for (int ni = 0; ni < 8; ni++) {
                        int j = ni * 8 + 2 * qc;
                        tr[(size_t)j * 132 + r]           = acc[mi][ni][0];
                        tr[(size_t)(j + 1) * 132 + r]     = acc[mi][ni][1];
                        tr[(size_t)j * 132 + r + 8]       = acc[mi][ni][2];
                        tr[(size_t)(j + 1) * 132 + r + 8] = acc[mi][ni][3];
                    }
                }
            }
            __syncthreads();
            for (int rr = wid; rr < 64; rr += 4) {
                int gr = bc * 128 + h * 64 + rr;
                float4 v = *(float4*)&tr[(size_t)rr * 132 + lid * 4];
                *(float4*)&g_sim[(size_t)gr * NN + br * 128 + lid * 4] = v;
            }
        }
    }
}

// ---------------------------------------------------------------------------
__device__ __forceinline__ float softplus_f(float z) {
    float e = __expf(-fabsf(z));
    return fmaxf(z, 0.f) + __logf(1.f + e);
}

// fused 5-value reduction: v[0..3] sums, v[4] min. 2 barriers total.
__device__ __forceinline__ void block_red5(float* v, float* sh) {
    #pragma unroll
    for (int o = 16; o; o >>= 1) {
        #pragma unroll
        for (int k = 0; k < 4; k++) v[k] += __shfl_xor_sync(0xffffffffu, v[k], o);
        v[4] = fminf(v[4], __shfl_xor_sync(0xffffffffu, v[4], o));
    }
    int w = threadIdx.x >> 5, l = threadIdx.x & 31;
    if (l == 0) {
        #pragma unroll
        for (int k = 0; k < 5; k++) sh[w * 5 + k] = v[k];
    }
    __syncthreads();
    if (threadIdx.x < 32) {
        #pragma unroll
        for (int k = 0; k < 4; k++) v[k] = (l < 8) ? sh[l * 5 + k] : 0.f;
        v[4] = (l < 8) ? sh[l * 5 + 4] : 1e30f;
        #pragma unroll
        for (int o = 4; o; o >>= 1) {
            #pragma unroll
            for (int k = 0; k < 4; k++) v[k] += __shfl_xor_sync(0xffffffffu, v[k], o);
            v[4] = fminf(v[4], __shfl_xor_sync(0xffffffffu, v[4], o));
        }
        if (l == 0) {
            #pragma unroll
            for (int k = 0; k < 5; k++) sh[k] = v[k];
        }
    }
    __syncthreads();
    #pragma unroll
    for (int k = 0; k < 5; k++) v[k] = sh[k];
}

template <int NV>
__device__ __forceinline__ void block_redN(float* v, float* sh) {
    #pragma unroll
    for (int o = 16; o; o >>= 1)
        #pragma unroll
        for (int k = 0; k < NV; k++) v[k] += __shfl_xor_sync(0xffffffffu, v[k], o);
    int w = threadIdx.x >> 5, l = threadIdx.x & 31;
    if (l == 0) {
        #pragma unroll
        for (int k = 0; k < NV; k++) sh[w * NV + k] = v[k];
    }
    __syncthreads();
    if (threadIdx.x < 32) {
        #pragma unroll
        for (int k = 0; k < NV; k++) v[k] = (l < 8) ? sh[l * NV + k] : 0.f;
        #pragma unroll
        for (int o = 4; o; o >>= 1)
            #pragma unroll
            for (int k = 0; k < NV; k++) v[k] += __shfl_xor_sync(0xffffffffu, v[k], o);
        if (l == 0) {
            #pragma unroll
            for (int k = 0; k < NV; k++) sh[k] = v[k];
        }
    }
    __syncthreads();
    #pragma unroll
    for (int k = 0; k < NV; k++) v[k] = sh[k];
}

// ---------------------------------------------------------------------------
// Kernel 2: per-row stats + loss + fused final reduction (last-block pattern).
// ---------------------------------------------------------------------------
__global__ void __launch_bounds__(256) rowstats(float* __restrict__ out) {
    const int i   = blockIdx.x;
    const int tid = threadIdx.x;

    __shared__ float red[48];
    __shared__ bool  s_last;

    float v[16];
    const float4* rp = (const float4*)&g_sim[(size_t)i * NN];
    #pragma unroll
    for (int q = 0; q < 4; q++) {
        float4 t = rp[tid + q * 256];
        v[q * 4 + 0] = t.x; v[q * 4 + 1] = t.y;
        v[q * 4 + 2] = t.z; v[q * 4 + 3] = t.w;
    }

    const int cls_lo = (i / KK) * KK;

    // pass 1: {ps, pq, ns, nq, pmin}
    float r5[5] = {0.f, 0.f, 0.f, 0.f, 1e30f};
    #pragma unroll
    for (int q = 0; q < 4; q++) {
        const int j0 = (tid + q * 256) * 4;
        const bool gin = ((unsigned)(j0 - cls_lo) < (unsigned)KK);
        float x0 = v[q*4+0], x1 = v[q*4+1], x2 = v[q*4+2], x3 = v[q*4+3];
        if (!gin) {
            r5[2] += (x0 + x1) + (x2 + x3);
            r5[3] += (x0*x0 + x1*x1) + (x2*x2 + x3*x3);
        } else {
            #pragma unroll
            for (int s = 0; s < 4; s++) {
                float x = v[q * 4 + s];
                if (j0 + s != i) { r5[0] += x; r5[1] += x * x; r5[4] = fminf(r5[4], x); }
            }
        }
    }
    block_red5(r5, red);
    const float ps = r5[0], ns = r5[2];

    const float p = (float)(KK - 1);
    const float m = (float)(NN - KK);
    float pmean = ps / p, nmean = ns / m;
    float pvar = fmaxf(r5[1] / p - pmean * pmean, 0.f);
    float nvar = fmaxf(r5[3] / m - nmean * nmean, 0.f);
    float psd = sqrtf(pvar), nsd = sqrtf(nvar);
    const float inter = 0.8f * (nsd * pmean + psd * nmean) / (psd + nsd) + 0.1f;
    const float th    = r5[4] - 0.05f;

    // pass 2: {psum, nsum, cnt}; skip softplus when 40(x-inter) < -10
    // (softplus(z) < 4.6e-5 there; contribution to loss < 3e-6, far below tol)
    const float xskip = inter - 0.25f;
    float r3[3] = {0.f, 0.f, 0.f};
    #pragma unroll
    for (int q = 0; q < 4; q++) {
        const int j0 = (tid + q * 256) * 4;
        const bool gin = ((unsigned)(j0 - cls_lo) < (unsigned)KK);
        if (!gin) {
            #pragma unroll
            for (int s = 0; s < 4; s++) {
                float x = v[q * 4 + s];
                if (x > th) {
                    r3[2] += 1.f;
                    if (x > xskip)
                        r3[1] += softplus_f(40.f * (x - inter));
                }
            }
        } else {
            #pragma unroll
            for (int s = 0; s < 4; s++) {
                float x = v[q * 4 + s];
                if (j0 + s != i) r3[0] += softplus_f(-10.f * (x - inter));
            }
        }
    }
    block_redN<3>(r3, red);

    if (tid == 0) {
        float loss = 0.f, invalid = 1.f;
        if (r3[2] > 0.f) {
            loss = 0.2f * r3[0] / p + 0.05f * r3[1] / r3[2];
            invalid = 0.f;
        }
        g_row[i] = make_float4(loss, invalid, ps, ns);
        __threadfence();
        unsigned int done = atomicAdd(&g_cnt, 1u);
        s_last = (done == (unsigned)(NN - 1));
    }
    __syncthreads();

    if (s_last) {
        __threadfence();
        float a[4] = {0.f, 0.f, 0.f, 0.f};
        for (int r = tid; r < NN; r += 256) {
            float4 t = g_row[r];
            a[0] += t.x; a[1] += t.y; a[2] += t.z; a[3] += t.w;
        }
        block_redN<4>(a, red);
        if (tid == 0) {
            out[0] = a[0] / (float)NN;
            out[1] = a[1] / (float)NN;
            out[2] = a[2] / (p * (float)NN);
            out[3] = a[3] / (m * (float)NN);
            g_cnt = 0;                      // reset for next graph replay
        }
    }
}

// ---------------------------------------------------------------------------
extern "C" void kernel_launch(void* const* d_in, const int* in_sizes, int n_in,
                              void* d_out, int out_size) {
    const float* X = (const float*)d_in[0];
    float* out = (float*)d_out;

    static bool attr_set = false;
    if (!attr_set) {
        cudaFuncSetAttribute(gemm_mma, cudaFuncAttributeMaxDynamicSharedMemorySize, 98304);
        attr_set = true;
    }

    split_bf16<<<NN * DD / 1024, 256>>>(X);
    gemm_mma<<<NCTAS, 128, 98304>>>();
    rowstats<<<NN, 256>>>(out);
}